// round 4
// baseline (speedup 1.0000x reference)
#include <cuda_runtime.h>
#include <cstdint>
#include <cstddef>

// out = (G @ W @ A) @ depthwise_conv3x3(x)
//   A = softmax(attention_weights, axis=1), G = softmax(global_attention_weight, axis=1)
//   W = pointwise_weights[:, :, 0, 0]
// x: [8, 64, 256, 256] f32; out same shape.

#define NCH 64
#define IMG 256
#define TH 4
#define TW 32
#define DWS_S 136          // pixel-row stride of dw tile; 136 % 32 == 8 -> conflict-free B frags

__device__ float g_M[NCH * NCH];   // fused mixing matrix M = G @ W @ A (tf32-rounded bits)

// ---------------------------------------------------------------------------
// helpers
// ---------------------------------------------------------------------------
__device__ __forceinline__ unsigned f2tf(float x) {
    unsigned r;
    asm("cvt.rna.tf32.f32 %0, %1;" : "=r"(r) : "f"(x));
    return r;
}

__device__ __forceinline__ void mma_tf32(float d[4], const unsigned a[4],
                                         unsigned b0, unsigned b1) {
    asm volatile(
        "mma.sync.aligned.m16n8k8.row.col.f32.tf32.tf32.f32 "
        "{%0,%1,%2,%3}, {%4,%5,%6,%7}, {%8,%9}, {%0,%1,%2,%3};\n"
        : "+f"(d[0]), "+f"(d[1]), "+f"(d[2]), "+f"(d[3])
        : "r"(a[0]), "r"(a[1]), "r"(a[2]), "r"(a[3]), "r"(b0), "r"(b1));
}

// ---------------------------------------------------------------------------
// Kernel 1: M = softmax(G) @ W @ softmax(A)  (one CTA, 256 threads; tiny)
// Stores M already rounded to tf32 so the fused kernel does zero cvts.
// ---------------------------------------------------------------------------
__global__ void compute_M_kernel(const float* __restrict__ aw,
                                 const float* __restrict__ gw,
                                 const float* __restrict__ pw) {
    __shared__ float As[NCH * NCH];
    __shared__ float Gs[NCH * NCH];
    __shared__ float Ts[NCH * NCH];
    float* red = Ts;  // reuse Ts as the reduction scratch during softmax phases

    const int t = threadIdx.x;       // 256 threads
    const int r = t >> 2, s = t & 3; // 4 threads per row

    // ---- softmax rows of aw -> As ----
    {
        const float* row = aw + r * NCH;
        float mx = -3.4e38f;
        for (int j = s; j < NCH; j += 4) mx = fmaxf(mx, row[j]);
        red[r * 4 + s] = mx;
        __syncthreads();
        mx = fmaxf(fmaxf(red[r * 4 + 0], red[r * 4 + 1]),
                   fmaxf(red[r * 4 + 2], red[r * 4 + 3]));
        __syncthreads();
        float sum = 0.f;
        for (int j = s; j < NCH; j += 4) {
            float e = __expf(row[j] - mx);
            As[r * NCH + j] = e;
            sum += e;
        }
        red[r * 4 + s] = sum;
        __syncthreads();
        sum = red[r * 4 + 0] + red[r * 4 + 1] + red[r * 4 + 2] + red[r * 4 + 3];
        float inv = 1.f / sum;
        for (int j = s; j < NCH; j += 4) As[r * NCH + j] *= inv;
        __syncthreads();
    }
    // ---- softmax rows of gw -> Gs ----
    {
        const float* row = gw + r * NCH;
        float mx = -3.4e38f;
        for (int j = s; j < NCH; j += 4) mx = fmaxf(mx, row[j]);
        red[r * 4 + s] = mx;
        __syncthreads();
        mx = fmaxf(fmaxf(red[r * 4 + 0], red[r * 4 + 1]),
                   fmaxf(red[r * 4 + 2], red[r * 4 + 3]));
        __syncthreads();
        float sum = 0.f;
        for (int j = s; j < NCH; j += 4) {
            float e = __expf(row[j] - mx);
            Gs[r * NCH + j] = e;
            sum += e;
        }
        red[r * 4 + s] = sum;
        __syncthreads();
        sum = red[r * 4 + 0] + red[r * 4 + 1] + red[r * 4 + 2] + red[r * 4 + 3];
        float inv = 1.f / sum;
        for (int j = s; j < NCH; j += 4) Gs[r * NCH + j] *= inv;
        __syncthreads();
    }
    // ---- Ts = W @ As ----  (overwrites the red scratch; synced above)
    float tloc[16];
    for (int ii = 0; ii < 16; ii++) {
        int e = t + ii * 256;
        int i = e >> 6, c = e & 63;
        float acc = 0.f;
        #pragma unroll 8
        for (int j = 0; j < NCH; j++)
            acc = fmaf(__ldg(pw + i * NCH + j), As[j * NCH + c], acc);
        tloc[ii] = acc;
    }
    __syncthreads();
    for (int ii = 0; ii < 16; ii++) Ts[t + ii * 256] = tloc[ii];
    __syncthreads();
    // ---- g_M = tf32(Gs @ Ts) ----
    for (int e = t; e < NCH * NCH; e += 256) {
        int k = e >> 6, c = e & 63;
        float acc = 0.f;
        #pragma unroll 8
        for (int j = 0; j < NCH; j++)
            acc = fmaf(Gs[k * NCH + j], Ts[j * NCH + c], acc);
        g_M[e] = __uint_as_float(f2tf(acc));
    }
}

// ---------------------------------------------------------------------------
// Kernel 2: fused depthwise-conv (global->reg via shuffles) + channel mix
//   grid (8, 64, 8), block 256.  Tile: 4x32 pixels, all 64 channels.
//   smem: dw tile only (34.8 KB) -> 3 CTAs/SM; single __syncthreads.
// ---------------------------------------------------------------------------
__global__ void __launch_bounds__(256, 3)
fused_kernel(const float* __restrict__ x, const float* __restrict__ dwwt,
             float* __restrict__ out) {
    __shared__ float dws[NCH * DWS_S];   // [64 channels][128 px] stride 136

    const int t    = threadIdx.x;
    const int lane = t & 31;
    const int wid  = t >> 5;
    const int b    = blockIdx.z;
    const int ty   = blockIdx.y, tx = blockIdx.x;
    const int y0   = ty * TH, x0 = tx * TW;

    // ------------------ depthwise 3x3 conv, warp-per-8-channels ------------
    {
        const int cBase = wid * 8;
        // edge-column index for lanes 0/1 (left col x0-1, right col x0+32)
        const int ecol = (lane == 0) ? (x0 - 1) : (x0 + TW);
        const bool eok = (lane < 2) && ((unsigned)ecol < (unsigned)IMG);

        #pragma unroll 2
        for (int i = 0; i < 8; i++) {
            const int c = cBase + i;
            const float* wp = dwwt + c * 9;
            const float w0 = __ldg(wp + 0), w1 = __ldg(wp + 1), w2 = __ldg(wp + 2);
            const float w3 = __ldg(wp + 3), w4 = __ldg(wp + 4), w5 = __ldg(wp + 5);
            const float w6 = __ldg(wp + 6), w7 = __ldg(wp + 7), w8 = __ldg(wp + 8);
            const float* xc = x + (((size_t)(b * NCH + c)) << 16);

            float o0 = 0.f, o1 = 0.f, o2 = 0.f, o3 = 0.f;
            float* drow = dws + c * DWS_S + lane;

            #pragma unroll
            for (int rr = 0; rr < 6; rr++) {
                const int y = y0 - 1 + rr;
                float v = 0.f, e = 0.f;
                if ((unsigned)y < (unsigned)IMG) {
                    v = __ldg(xc + y * IMG + x0 + lane);
                    if (eok) e = __ldg(xc + y * IMG + ecol);
                }
                const float bL = __shfl_sync(0xffffffffu, e, 0);
                const float bR = __shfl_sync(0xffffffffu, e, 1);
                float vL = __shfl_up_sync(0xffffffffu, v, 1);
                if (lane == 0) vL = bL;
                float vR = __shfl_down_sync(0xffffffffu, v, 1);
                if (lane == 31) vR = bR;

                // input row y contributes:
                //   weight row 0 -> out row (y+1) = tile row rr
                //   weight row 1 -> out row (y)   = tile row rr-1
                //   weight row 2 -> out row (y-1) = tile row rr-2
                if (rr <= 3) {  // row0 taps into o[rr]
                    float* o = (rr == 0) ? &o0 : (rr == 1) ? &o1 : (rr == 2) ? &o2 : &o3;
                    *o = fmaf(w0, vL, fmaf(w1, v, fmaf(w2, vR, *o)));
                }
                if (rr >= 1 && rr <= 4) {  // row1 taps into o[rr-1]
                    float* o = (rr == 1) ? &o0 : (rr == 2) ? &o1 : (rr == 3) ? &o2 : &o3;
                    *o = fmaf(w3, vL, fmaf(w4, v, fmaf(w5, vR, *o)));
                }
                if (rr >= 2) {  // row2 taps into o[rr-2], which is then complete
                    float* o = (rr == 2) ? &o0 : (rr == 3) ? &o1 : (rr == 4) ? &o2 : &o3;
                    *o = fmaf(w6, vL, fmaf(w7, v, fmaf(w8, vR, *o)));
                    drow[(rr - 2) * TW] = __uint_as_float(f2tf(*o));
                }
            }
        }
    }

    // ---- A fragments: M[warpM*16 .. +16][0..64) in registers (L2-hot) ----
    const int warpM = wid & 3;       // 4 groups of 16 out-channels
    const int warpN = wid >> 2;      // 2 groups of 64 pixels
    const int g = lane >> 2, m = lane & 3;

    unsigned afr[8][4];
    {
        const int r0 = warpM * 16 + g;
        #pragma unroll
        for (int ks = 0; ks < 8; ks++) {
            int col = ks * 8 + m;
            afr[ks][0] = __float_as_uint(__ldg(g_M + r0 * NCH + col));
            afr[ks][1] = __float_as_uint(__ldg(g_M + (r0 + 8) * NCH + col));
            afr[ks][2] = __float_as_uint(__ldg(g_M + r0 * NCH + col + 4));
            afr[ks][3] = __float_as_uint(__ldg(g_M + (r0 + 8) * NCH + col + 4));
        }
    }

    __syncthreads();   // dws ready

    // ---- channel mix: out[64,128] = M @ dw  via m16n8k8 tf32 MMA ----
    const size_t outBase = ((size_t)(b * NCH)) * (IMG * IMG)
                         + (size_t)y0 * IMG + x0;
    #pragma unroll
    for (int pair = 0; pair < 4; pair++) {
        const int pb0 = warpN * 64 + pair * 16;   // two n-chunks: pb0, pb0+8
        float acc0[4] = {0.f, 0.f, 0.f, 0.f};
        float acc1[4] = {0.f, 0.f, 0.f, 0.f};
        #pragma unroll
        for (int ks = 0; ks < 8; ks++) {
            const float* bp = dws + (ks * 8 + m) * DWS_S;
            unsigned b0a = __float_as_uint(bp[pb0 + g]);
            unsigned b1a = __float_as_uint(bp[4 * DWS_S + pb0 + g]);
            unsigned b0b = __float_as_uint(bp[pb0 + 8 + g]);
            unsigned b1b = __float_as_uint(bp[4 * DWS_S + pb0 + 8 + g]);
            mma_tf32(acc0, afr[ks], b0a, b1a);
            mma_tf32(acc1, afr[ks], b0b, b1b);
        }
        const int och = warpM * 16 + g;
        const int p0 = pb0 + 2 * m;
        const int p1 = pb0 + 8 + 2 * m;

        {
            size_t off = outBase + (size_t)och * (IMG * IMG) + (p0 >> 5) * IMG + (p0 & 31);
            *reinterpret_cast<float2*>(out + off) = make_float2(acc0[0], acc0[1]);
        }
        {
            size_t off = outBase + (size_t)(och + 8) * (IMG * IMG) + (p0 >> 5) * IMG + (p0 & 31);
            *reinterpret_cast<float2*>(out + off) = make_float2(acc0[2], acc0[3]);
        }
        {
            size_t off = outBase + (size_t)och * (IMG * IMG) + (p1 >> 5) * IMG + (p1 & 31);
            *reinterpret_cast<float2*>(out + off) = make_float2(acc1[0], acc1[1]);
        }
        {
            size_t off = outBase + (size_t)(och + 8) * (IMG * IMG) + (p1 >> 5) * IMG + (p1 & 31);
            *reinterpret_cast<float2*>(out + off) = make_float2(acc1[2], acc1[3]);
        }
    }
}

// ---------------------------------------------------------------------------
extern "C" void kernel_launch(void* const* d_in, const int* in_sizes, int n_in,
                              void* d_out, int out_size) {
    const float* x   = (const float*)d_in[0];   // [8,64,256,256]
    const float* dww = (const float*)d_in[1];   // [64,1,3,3]
    const float* pww = (const float*)d_in[2];   // [64,64,1,1]
    const float* aw  = (const float*)d_in[3];   // [64,64]
    const float* gw  = (const float*)d_in[4];   // [64,64]
    float* out = (float*)d_out;

    compute_M_kernel<<<1, 256>>>(aw, gw, pww);

    dim3 grid(IMG / TW, IMG / TH, 8);
    fused_kernel<<<grid, 256>>>(x, dww, out);
}

// round 6
// speedup vs baseline: 1.7762x; 1.7762x over previous
#include <cuda_runtime.h>
#include <cstdint>
#include <cstddef>

// out = (G @ W @ A) @ depthwise_conv3x3(x)
//   A = softmax(attention_weights, axis=1), G = softmax(global_attention_weight, axis=1)
//   W = pointwise_weights[:, :, 0, 0]
// x: [8, 64, 256, 256] f32; out same shape.

#define NCH 64
#define IMG 256
#define TW 128             // tile: 1 row x 128 cols x 64 channels
#define DWS_S 136          // row stride of dw tile; 136 % 32 == 8 -> conflict-free B frags

__device__ float g_M[NCH * NCH];   // fused mixing matrix M = G @ W @ A (tf32-rounded bits)

// ---------------------------------------------------------------------------
// helpers
// ---------------------------------------------------------------------------
__device__ __forceinline__ unsigned f2tf(float x) {
    unsigned r;
    asm("cvt.rna.tf32.f32 %0, %1;" : "=r"(r) : "f"(x));
    return r;
}

__device__ __forceinline__ void mma_tf32(float d[4], const unsigned a[4],
                                         unsigned b0, unsigned b1) {
    asm volatile(
        "mma.sync.aligned.m16n8k8.row.col.f32.tf32.tf32.f32 "
        "{%0,%1,%2,%3}, {%4,%5,%6,%7}, {%8,%9}, {%0,%1,%2,%3};\n"
        : "+f"(d[0]), "+f"(d[1]), "+f"(d[2]), "+f"(d[3])
        : "r"(a[0]), "r"(a[1]), "r"(a[2]), "r"(a[3]), "r"(b0), "r"(b1));
}

// ---------------------------------------------------------------------------
// Kernel 1: M = softmax(G) @ W @ softmax(A)  (one CTA, 256 threads; tiny)
// Stores M already rounded to tf32 so the fused kernel does zero cvts.
// ---------------------------------------------------------------------------
__global__ void compute_M_kernel(const float* __restrict__ aw,
                                 const float* __restrict__ gw,
                                 const float* __restrict__ pw) {
    __shared__ float As[NCH * NCH];
    __shared__ float Gs[NCH * NCH];
    __shared__ float Ts[NCH * NCH];
    float* red = Ts;  // reuse Ts as the reduction scratch during softmax phases

    const int t = threadIdx.x;       // 256 threads
    const int r = t >> 2, s = t & 3; // 4 threads per row

    // ---- softmax rows of aw -> As ----
    {
        const float* row = aw + r * NCH;
        float mx = -3.4e38f;
        for (int j = s; j < NCH; j += 4) mx = fmaxf(mx, row[j]);
        red[r * 4 + s] = mx;
        __syncthreads();
        mx = fmaxf(fmaxf(red[r * 4 + 0], red[r * 4 + 1]),
                   fmaxf(red[r * 4 + 2], red[r * 4 + 3]));
        __syncthreads();
        float sum = 0.f;
        for (int j = s; j < NCH; j += 4) {
            float e = __expf(row[j] - mx);
            As[r * NCH + j] = e;
            sum += e;
        }
        red[r * 4 + s] = sum;
        __syncthreads();
        sum = red[r * 4 + 0] + red[r * 4 + 1] + red[r * 4 + 2] + red[r * 4 + 3];
        float inv = 1.f / sum;
        for (int j = s; j < NCH; j += 4) As[r * NCH + j] *= inv;
        __syncthreads();
    }
    // ---- softmax rows of gw -> Gs ----
    {
        const float* row = gw + r * NCH;
        float mx = -3.4e38f;
        for (int j = s; j < NCH; j += 4) mx = fmaxf(mx, row[j]);
        red[r * 4 + s] = mx;
        __syncthreads();
        mx = fmaxf(fmaxf(red[r * 4 + 0], red[r * 4 + 1]),
                   fmaxf(red[r * 4 + 2], red[r * 4 + 3]));
        __syncthreads();
        float sum = 0.f;
        for (int j = s; j < NCH; j += 4) {
            float e = __expf(row[j] - mx);
            Gs[r * NCH + j] = e;
            sum += e;
        }
        red[r * 4 + s] = sum;
        __syncthreads();
        sum = red[r * 4 + 0] + red[r * 4 + 1] + red[r * 4 + 2] + red[r * 4 + 3];
        float inv = 1.f / sum;
        for (int j = s; j < NCH; j += 4) Gs[r * NCH + j] *= inv;
        __syncthreads();
    }
    // ---- Ts = W @ As ----  (overwrites the red scratch; synced above)
    float tloc[16];
    for (int ii = 0; ii < 16; ii++) {
        int e = t + ii * 256;
        int i = e >> 6, c = e & 63;
        float acc = 0.f;
        #pragma unroll 8
        for (int j = 0; j < NCH; j++)
            acc = fmaf(__ldg(pw + i * NCH + j), As[j * NCH + c], acc);
        tloc[ii] = acc;
    }
    __syncthreads();
    for (int ii = 0; ii < 16; ii++) Ts[t + ii * 256] = tloc[ii];
    __syncthreads();
    // ---- g_M = tf32(Gs @ Ts) ----
    for (int e = t; e < NCH * NCH; e += 256) {
        int k = e >> 6, c = e & 63;
        float acc = 0.f;
        #pragma unroll 8
        for (int j = 0; j < NCH; j++)
            acc = fmaf(Gs[k * NCH + j], Ts[j * NCH + c], acc);
        g_M[e] = __uint_as_float(f2tf(acc));
    }
}

// ---------------------------------------------------------------------------
// Kernel 2: fused depthwise-conv (vectorized global->reg) + channel mix
//   grid (2, 256, 8), block 256.  Tile: 1 row x 128 cols, all 64 channels.
//   Warp owns 8 channels; per channel 3 x LDG.128 rows + 2 boundary shuffles.
// ---------------------------------------------------------------------------
__global__ void __launch_bounds__(256, 3)
fused_kernel(const float* __restrict__ x, const float* __restrict__ dwwt,
             float* __restrict__ out) {
    __shared__ float dws[NCH * DWS_S];   // [64 channels][128 px] stride 136

    const int t    = threadIdx.x;
    const int lane = t & 31;
    const int wid  = t >> 5;
    const int b    = blockIdx.z;
    const int y0   = blockIdx.y;          // output row
    const int x0   = blockIdx.x * TW;     // output col base

    // ------------------ depthwise 3x3 conv, warp-per-8-channels ------------
    {
        const int cBase = wid * 8;
        const float* xbase = x + (((size_t)(b * NCH + cBase)) << 16)
                           + x0 + 4 * lane;

        #pragma unroll 2
        for (int i = 0; i < 8; i++) {
            const int c = cBase + i;
            const float* xc = xbase + ((size_t)i << 16);
            const float* wp = dwwt + c * 9;
            float w[9];
            #pragma unroll
            for (int k = 0; k < 9; k++) w[k] = __ldg(wp + k);

            // 3 input rows, each warp-row = 512B coalesced vector load
            float4 v[3];
            #pragma unroll
            for (int k = 0; k < 3; k++) {
                const int yk = y0 - 1 + k;
                if ((unsigned)yk < (unsigned)IMG)
                    v[k] = __ldg((const float4*)(xc + yk * IMG - 4 * lane + 4 * lane)); // = xc + yk*IMG
                else
                    v[k] = make_float4(0.f, 0.f, 0.f, 0.f);
            }
            // edge columns: lanes 0..2 -> left col rows 0..2, lanes 3..5 -> right col
            float e = 0.f;
            {
                const int kk = (lane < 3) ? lane : lane - 3;
                const int ec = (lane < 3) ? (x0 - 1) : (x0 + TW);
                const int ey = y0 - 1 + kk;
                if (lane < 6 && (unsigned)ec < (unsigned)IMG &&
                    (unsigned)ey < (unsigned)IMG)
                    e = __ldg(x + (((size_t)(b * NCH + c)) << 16) + ey * IMG + ec);
            }

            float4 o = make_float4(0.f, 0.f, 0.f, 0.f);
            #pragma unroll
            for (int k = 0; k < 3; k++) {
                float fL = __shfl_up_sync(0xffffffffu, v[k].w, 1);
                const float eL = __shfl_sync(0xffffffffu, e, k);
                if (lane == 0) fL = eL;
                float fR = __shfl_down_sync(0xffffffffu, v[k].x, 1);
                const float eR = __shfl_sync(0xffffffffu, e, 3 + k);
                if (lane == 31) fR = eR;
                const float wa = w[3 * k], wb = w[3 * k + 1], wc = w[3 * k + 2];
                o.x = fmaf(wa, fL,     fmaf(wb, v[k].x, fmaf(wc, v[k].y, o.x)));
                o.y = fmaf(wa, v[k].x, fmaf(wb, v[k].y, fmaf(wc, v[k].z, o.y)));
                o.z = fmaf(wa, v[k].y, fmaf(wb, v[k].z, fmaf(wc, v[k].w, o.z)));
                o.w = fmaf(wa, v[k].z, fmaf(wb, v[k].w, fmaf(wc, fR,     o.w)));
            }
            float4 os;
            os.x = __uint_as_float(f2tf(o.x));
            os.y = __uint_as_float(f2tf(o.y));
            os.z = __uint_as_float(f2tf(o.z));
            os.w = __uint_as_float(f2tf(o.w));
            *reinterpret_cast<float4*>(dws + c * DWS_S + 4 * lane) = os;
        }
    }

    // ---- A fragments: M[warpM*16 .. +16][0..64) in registers (L2-hot) ----
    const int warpM = wid & 3;       // 4 groups of 16 out-channels
    const int warpN = wid >> 2;      // 2 groups of 64 pixels
    const int g = lane >> 2, m = lane & 3;

    unsigned afr[8][4];
    {
        const int r0 = warpM * 16 + g;
        #pragma unroll
        for (int ks = 0; ks < 8; ks++) {
            int col = ks * 8 + m;
            afr[ks][0] = __float_as_uint(__ldg(g_M + r0 * NCH + col));
            afr[ks][1] = __float_as_uint(__ldg(g_M + (r0 + 8) * NCH + col));
            afr[ks][2] = __float_as_uint(__ldg(g_M + r0 * NCH + col + 4));
            afr[ks][3] = __float_as_uint(__ldg(g_M + (r0 + 8) * NCH + col + 4));
        }
    }

    __syncthreads();   // dws ready

    // ---- channel mix: out[64,128] = M @ dw  via m16n8k8 tf32 MMA ----
    const size_t outBase = (((size_t)(b * NCH)) << 16) + (size_t)y0 * IMG + x0;
    #pragma unroll
    for (int pair = 0; pair < 4; pair++) {
        const int pb0 = warpN * 64 + pair * 16;   // two n-chunks: pb0, pb0+8
        float acc0[4] = {0.f, 0.f, 0.f, 0.f};
        float acc1[4] = {0.f, 0.f, 0.f, 0.f};
        #pragma unroll
        for (int ks = 0; ks < 8; ks++) {
            const float* bp = dws + (ks * 8 + m) * DWS_S;
            unsigned b0a = __float_as_uint(bp[pb0 + g]);
            unsigned b1a = __float_as_uint(bp[4 * DWS_S + pb0 + g]);
            unsigned b0b = __float_as_uint(bp[pb0 + 8 + g]);
            unsigned b1b = __float_as_uint(bp[4 * DWS_S + pb0 + 8 + g]);
            mma_tf32(acc0, afr[ks], b0a, b1a);
            mma_tf32(acc1, afr[ks], b0b, b1b);
        }
        const int och = warpM * 16 + g;
        const int p0 = pb0 + 2 * m;        // column offsets within the 128-px row
        const int p1 = pb0 + 8 + 2 * m;

        {
            size_t off = outBase + ((size_t)och << 16) + p0;
            *reinterpret_cast<float2*>(out + off) = make_float2(acc0[0], acc0[1]);
        }
        {
            size_t off = outBase + ((size_t)(och + 8) << 16) + p0;
            *reinterpret_cast<float2*>(out + off) = make_float2(acc0[2], acc0[3]);
        }
        {
            size_t off = outBase + ((size_t)och << 16) + p1;
            *reinterpret_cast<float2*>(out + off) = make_float2(acc1[0], acc1[1]);
        }
        {
            size_t off = outBase + ((size_t)(och + 8) << 16) + p1;
            *reinterpret_cast<float2*>(out + off) = make_float2(acc1[2], acc1[3]);
        }
    }
}

// ---------------------------------------------------------------------------
extern "C" void kernel_launch(void* const* d_in, const int* in_sizes, int n_in,
                              void* d_out, int out_size) {
    const float* x   = (const float*)d_in[0];   // [8,64,256,256]
    const float* dww = (const float*)d_in[1];   // [64,1,3,3]
    const float* pww = (const float*)d_in[2];   // [64,64,1,1]
    const float* aw  = (const float*)d_in[3];   // [64,64]
    const float* gw  = (const float*)d_in[4];   // [64,64]
    float* out = (float*)d_out;

    compute_M_kernel<<<1, 256>>>(aw, gw, pww);

    dim3 grid(IMG / TW, IMG, 8);
    fused_kernel<<<grid, 256>>>(x, dww, out);
}

// round 8
// speedup vs baseline: 2.5407x; 1.4304x over previous
#include <cuda_runtime.h>
#include <cstdint>
#include <cstddef>

// out = (G @ W @ A) @ depthwise_conv3x3(x)
// x: [8, 64, 256, 256] f32; out same shape.

#define NCH 64
#define IMG 256
#define TW 128
#define TH 2
#define DWS_S 264          // row stride (floats); 264 % 32 == 8 -> conflict-free B frags
#define SMEM_BYTES (NCH * DWS_S * 4)   // 67584 B

__device__ float g_Mp[8 * 4 * NCH * 2];   // M packed as [ks][m][row][2] tf32 fragments
__constant__ float c_dw[NCH * 9];         // depthwise weights (warp-uniform -> const cache)

// ---------------------------------------------------------------------------
__device__ __forceinline__ unsigned f2tf(float x) {
    unsigned r;
    asm("cvt.rna.tf32.f32 %0, %1;" : "=r"(r) : "f"(x));
    return r;
}

__device__ __forceinline__ void mma_tf32(float d[4], const unsigned* a,
                                         unsigned b0, unsigned b1) {
    asm volatile(
        "mma.sync.aligned.m16n8k8.row.col.f32.tf32.tf32.f32 "
        "{%0,%1,%2,%3}, {%4,%5,%6,%7}, {%8,%9}, {%0,%1,%2,%3};\n"
        : "+f"(d[0]), "+f"(d[1]), "+f"(d[2]), "+f"(d[3])
        : "r"(a[0]), "r"(a[1]), "r"(a[2]), "r"(a[3]), "r"(b0), "r"(b1));
}

// ---------------------------------------------------------------------------
// Kernel 1: M = softmax(G) @ W @ softmax(A), packed into fragment order.
// 1024 threads so the two 64^3 matmuls use 32 warps, not 8.
// ---------------------------------------------------------------------------
__global__ void compute_M_kernel(const float* __restrict__ aw,
                                 const float* __restrict__ gw,
                                 const float* __restrict__ pw) {
    __shared__ float As[NCH * NCH];
    __shared__ float Gs[NCH * NCH];
    __shared__ float Ts[NCH * NCH];
    float* red = Ts;   // 1024-float reduction scratch (reused)

    const int t = threadIdx.x;         // 1024 threads
    const int r = t >> 4, s = t & 15;  // 16 threads per row

    // ---- softmax rows of aw -> As ----
    {
        const float* row = aw + r * NCH;
        float mx = -3.4e38f;
        for (int j = s; j < NCH; j += 16) mx = fmaxf(mx, row[j]);
        red[r * 16 + s] = mx;
        __syncthreads();
        mx = -3.4e38f;
        #pragma unroll
        for (int k = 0; k < 16; k++) mx = fmaxf(mx, red[r * 16 + k]);
        __syncthreads();
        float sum = 0.f;
        for (int j = s; j < NCH; j += 16) {
            float e = __expf(row[j] - mx);
            As[r * NCH + j] = e;
            sum += e;
        }
        red[r * 16 + s] = sum;
        __syncthreads();
        sum = 0.f;
        #pragma unroll
        for (int k = 0; k < 16; k++) sum += red[r * 16 + k];
        float inv = 1.f / sum;
        for (int j = s; j < NCH; j += 16) As[r * NCH + j] *= inv;
        __syncthreads();
    }
    // ---- softmax rows of gw -> Gs ----
    {
        const float* row = gw + r * NCH;
        float mx = -3.4e38f;
        for (int j = s; j < NCH; j += 16) mx = fmaxf(mx, row[j]);
        red[r * 16 + s] = mx;
        __syncthreads();
        mx = -3.4e38f;
        #pragma unroll
        for (int k = 0; k < 16; k++) mx = fmaxf(mx, red[r * 16 + k]);
        __syncthreads();
        float sum = 0.f;
        for (int j = s; j < NCH; j += 16) {
            float e = __expf(row[j] - mx);
            Gs[r * NCH + j] = e;
            sum += e;
        }
        red[r * 16 + s] = sum;
        __syncthreads();
        sum = 0.f;
        #pragma unroll
        for (int k = 0; k < 16; k++) sum += red[r * 16 + k];
        float inv = 1.f / sum;
        for (int j = s; j < NCH; j += 16) Gs[r * NCH + j] *= inv;
        __syncthreads();
    }
    // ---- Ts = W @ As ----
    float tloc[4];
    #pragma unroll
    for (int ii = 0; ii < 4; ii++) {
        int e = t + ii * 1024;
        int i = e >> 6, c = e & 63;
        float acc = 0.f;
        #pragma unroll 8
        for (int j = 0; j < NCH; j++)
            acc = fmaf(__ldg(pw + i * NCH + j), As[j * NCH + c], acc);
        tloc[ii] = acc;
    }
    __syncthreads();
    #pragma unroll
    for (int ii = 0; ii < 4; ii++) Ts[t + ii * 1024] = tloc[ii];
    __syncthreads();
    // ---- g_Mp = pack(tf32(Gs @ Ts)) ----
    #pragma unroll
    for (int ii = 0; ii < 4; ii++) {
        int e = t + ii * 1024;
        int k = e >> 6, c = e & 63;   // row k (out-ch), col c (in-ch)
        float acc = 0.f;
        #pragma unroll 8
        for (int j = 0; j < NCH; j++)
            acc = fmaf(Gs[k * NCH + j], Ts[j * NCH + c], acc);
        int ks = c >> 3, w = c & 7, mm = w & 3, h = w >> 2;
        g_Mp[(((ks * 4 + mm) * NCH) + k) * 2 + h] = __uint_as_float(f2tf(acc));
    }
}

// ---------------------------------------------------------------------------
// Kernel 2: fused depthwise-conv + channel mix
//   grid (2, 128, 8), block 256.  Tile: 2 rows x 128 cols, all 64 channels.
//   M=32 per warp (2 m16 tiles share B fragments); weights in __constant__.
// ---------------------------------------------------------------------------
__global__ void __launch_bounds__(256, 2)
fused_kernel(const float* __restrict__ x, float* __restrict__ out) {
    extern __shared__ float dws[];   // [64 ch][256 px] stride 264

    const int t    = threadIdx.x;
    const int lane = t & 31;
    const int wid  = t >> 5;
    const int b    = blockIdx.z;
    const int y0   = blockIdx.y * TH;
    const int x0   = blockIdx.x * TW;

    // ------------------ depthwise 3x3 conv, warp-per-8-channels ------------
    {
        const int cBase = wid * 8;
        const float* xbase = x + (((size_t)(b * NCH + cBase)) << 16);
        const int ecol = (lane < 4) ? (x0 - 1) : (x0 + TW);
        const int erow = y0 - 1 + (lane & 3);
        const bool eok = (lane < 8) && ((unsigned)ecol < (unsigned)IMG) &&
                         ((unsigned)erow < (unsigned)IMG);

        #pragma unroll 2
        for (int i = 0; i < 8; i++) {
            const int c = cBase + i;
            const float* xc = xbase + ((size_t)i << 16);

            float4 v[4];
            #pragma unroll
            for (int k = 0; k < 4; k++) {
                const int yk = y0 - 1 + k;
                v[k] = ((unsigned)yk < (unsigned)IMG)
                     ? __ldg((const float4*)(xc + yk * IMG + x0) + lane)
                     : make_float4(0.f, 0.f, 0.f, 0.f);
            }
            const float e = eok ? __ldg(xc + erow * IMG + ecol) : 0.f;

            float4 ot = make_float4(0.f, 0.f, 0.f, 0.f);
            float4 ob = make_float4(0.f, 0.f, 0.f, 0.f);
            #pragma unroll
            for (int k = 0; k < 4; k++) {
                float fL = __shfl_up_sync(0xffffffffu, v[k].w, 1);
                const float eL = __shfl_sync(0xffffffffu, e, k);
                if (lane == 0) fL = eL;
                float fR = __shfl_down_sync(0xffffffffu, v[k].x, 1);
                const float eR = __shfl_sync(0xffffffffu, e, 4 + k);
                if (lane == 31) fR = eR;
                if (k <= 2) {   // weight row k -> top output row
                    const float wa = c_dw[c * 9 + 3 * k];
                    const float wb = c_dw[c * 9 + 3 * k + 1];
                    const float wc = c_dw[c * 9 + 3 * k + 2];
                    ot.x = fmaf(wa, fL,     fmaf(wb, v[k].x, fmaf(wc, v[k].y, ot.x)));
                    ot.y = fmaf(wa, v[k].x, fmaf(wb, v[k].y, fmaf(wc, v[k].z, ot.y)));
                    ot.z = fmaf(wa, v[k].y, fmaf(wb, v[k].z, fmaf(wc, v[k].w, ot.z)));
                    ot.w = fmaf(wa, v[k].z, fmaf(wb, v[k].w, fmaf(wc, fR,     ot.w)));
                }
                if (k >= 1) {   // weight row k-1 -> bottom output row
                    const float wa = c_dw[c * 9 + 3 * (k - 1)];
                    const float wb = c_dw[c * 9 + 3 * (k - 1) + 1];
                    const float wc = c_dw[c * 9 + 3 * (k - 1) + 2];
                    ob.x = fmaf(wa, fL,     fmaf(wb, v[k].x, fmaf(wc, v[k].y, ob.x)));
                    ob.y = fmaf(wa, v[k].x, fmaf(wb, v[k].y, fmaf(wc, v[k].z, ob.y)));
                    ob.z = fmaf(wa, v[k].y, fmaf(wb, v[k].z, fmaf(wc, v[k].w, ob.z)));
                    ob.w = fmaf(wa, v[k].z, fmaf(wb, v[k].w, fmaf(wc, fR,     ob.w)));
                }
            }
            float4 st;
            st.x = __uint_as_float(f2tf(ot.x));
            st.y = __uint_as_float(f2tf(ot.y));
            st.z = __uint_as_float(f2tf(ot.z));
            st.w = __uint_as_float(f2tf(ot.w));
            *reinterpret_cast<float4*>(dws + c * DWS_S + 4 * lane) = st;
            st.x = __uint_as_float(f2tf(ob.x));
            st.y = __uint_as_float(f2tf(ob.y));
            st.z = __uint_as_float(f2tf(ob.z));
            st.w = __uint_as_float(f2tf(ob.w));
            *reinterpret_cast<float4*>(dws + c * DWS_S + TW + 4 * lane) = st;
        }
    }

    // ---- A fragments: warp owns 32 out-channels (2 m16 tiles), resident ----
    const int warpM = wid & 1;       // 2 groups of 32 out-channels
    const int warpN = wid >> 1;      // 4 groups of 64 pixels
    const int g = lane >> 2, m = lane & 3;
    const int r0 = warpM * 32 + g;

    unsigned afr[8][8];
    {
        const float2* Mp = (const float2*)g_Mp;
        #pragma unroll
        for (int ks = 0; ks < 8; ks++) {
            const float2* pk = Mp + (ks * 4 + m) * NCH;
            float2 a0 = __ldg(pk + r0);
            float2 a1 = __ldg(pk + r0 + 8);
            float2 a2 = __ldg(pk + r0 + 16);
            float2 a3 = __ldg(pk + r0 + 24);
            afr[ks][0] = __float_as_uint(a0.x);
            afr[ks][1] = __float_as_uint(a1.x);
            afr[ks][2] = __float_as_uint(a0.y);
            afr[ks][3] = __float_as_uint(a1.y);
            afr[ks][4] = __float_as_uint(a2.x);
            afr[ks][5] = __float_as_uint(a3.x);
            afr[ks][6] = __float_as_uint(a2.y);
            afr[ks][7] = __float_as_uint(a3.y);
        }
    }

    __syncthreads();   // dws ready

    // ---- channel mix: out[64,256] = M @ dw  via m16n8k8 tf32 MMA ----
    #pragma unroll
    for (int pair = 0; pair < 4; pair++) {
        const int pb0 = warpN * 64 + pair * 16;
        float acc[4][4] = {};   // [t0c0, t0c1, t1c0, t1c1]
        #pragma unroll
        for (int ks = 0; ks < 8; ks++) {
            const float* bp = dws + (ks * 8 + m) * DWS_S;
            unsigned b0a = __float_as_uint(bp[pb0 + g]);
            unsigned b1a = __float_as_uint(bp[4 * DWS_S + pb0 + g]);
            unsigned b0b = __float_as_uint(bp[pb0 + 8 + g]);
            unsigned b1b = __float_as_uint(bp[4 * DWS_S + pb0 + 8 + g]);
            mma_tf32(acc[0], afr[ks] + 0, b0a, b1a);
            mma_tf32(acc[1], afr[ks] + 0, b0b, b1b);
            mma_tf32(acc[2], afr[ks] + 4, b0a, b1a);
            mma_tf32(acc[3], afr[ks] + 4, b0b, b1b);
        }
        #pragma unroll
        for (int cc = 0; cc < 2; cc++) {
            const int p  = pb0 + 8 * cc + 2 * m;
            const int yy = y0 + (p >> 7);
            const int xx = x0 + (p & 127);
            #pragma unroll
            for (int tt = 0; tt < 2; tt++) {
                const int och = warpM * 32 + g + 16 * tt;
                const float* a = acc[2 * tt + cc];
                size_t o1 = (((size_t)(b * NCH + och)) << 16) + yy * IMG + xx;
                *reinterpret_cast<float2*>(out + o1) = make_float2(a[0], a[1]);
                size_t o2 = (((size_t)(b * NCH + och + 8)) << 16) + yy * IMG + xx;
                *reinterpret_cast<float2*>(out + o2) = make_float2(a[2], a[3]);
            }
        }
    }
}

// ---------------------------------------------------------------------------
extern "C" void kernel_launch(void* const* d_in, const int* in_sizes, int n_in,
                              void* d_out, int out_size) {
    const float* x   = (const float*)d_in[0];   // [8,64,256,256]
    const float* dww = (const float*)d_in[1];   // [64,1,3,3]
    const float* pww = (const float*)d_in[2];   // [64,64,1,1]
    const float* aw  = (const float*)d_in[3];   // [64,64]
    const float* gw  = (const float*)d_in[4];   // [64,64]
    float* out = (float*)d_out;

    cudaMemcpyToSymbolAsync(c_dw, dww, NCH * 9 * sizeof(float), 0,
                            cudaMemcpyDeviceToDevice);
    compute_M_kernel<<<1, 1024>>>(aw, gw, pww);

    cudaFuncSetAttribute(fused_kernel,
                         cudaFuncAttributeMaxDynamicSharedMemorySize, SMEM_BYTES);
    dim3 grid(IMG / TW, IMG / TH, 8);
    fused_kernel<<<grid, 256, SMEM_BYTES>>>(x, out);
}